// round 5
// baseline (speedup 1.0000x reference)
#include <cuda_runtime.h>
#include <cuda_fp16.h>
#include <cstdint>

#define MOD_SCALE 0.04419417382415922f   /* 1/sqrt(512) */
#define CONV_SCALE 0.014731391274719739f /* 1/sqrt(512*9) */

// ---------------- device scratch ----------------
__device__ __align__(16) __half g_Xs[16 * 64 * 64 * 512]; // NHWC x*s fp16
__device__ __align__(16) __half g_Wh[9 * 512 * 512];      // [tap][co][ci] fp16
__device__ float  g_W2[512 * 512];
__device__ float  g_s[16 * 512];
__device__ float  g_alpha[16 * 512];

// ---------------- fused kernel A: mod (blocks 0-1023) + weight prep (1024-2047) ----------------
__global__ void prepA_kernel(const float* __restrict__ style,
                             const float* __restrict__ mw,
                             const float* __restrict__ bias,
                             const float* __restrict__ weight) {
    if (blockIdx.x < 1024) {
        int warp = (blockIdx.x * 256 + threadIdx.x) >> 5;
        int lane = threadIdx.x & 31;
        int b = warp >> 9, ci = warp & 511;
        float sum = 0.f;
        const float* st = style + b * 512;
        const float* w  = mw + ci * 512;
        for (int d = lane; d < 512; d += 32) sum += st[d] * w[d];
        #pragma unroll
        for (int off = 16; off > 0; off >>= 1) sum += __shfl_xor_sync(0xffffffffu, sum, off);
        if (lane == 0) g_s[b * 512 + ci] = sum * MOD_SCALE + bias[ci];
    } else {
        int idx = (blockIdx.x - 1024) * 256 + threadIdx.x;  // co*512+ci
        const float* w = weight + (size_t)idx * 9;
        float s2 = 0.f;
        #pragma unroll
        for (int k = 0; k < 9; k++) {
            float v = w[k];
            s2 += v * v;
            g_Wh[k * (512 * 512) + idx] = __float2half(v);
        }
        g_W2[idx] = s2;
    }
}

// ---------------- fused kernel B: demod alpha (blocks 0-1023) + Xs build (1024+) ----------------
__global__ void prepB_kernel(const float* __restrict__ x) {
    __shared__ float sm[32][65];
    __shared__ float ss[32];
    if (blockIdx.x < 1024) {
        int warp = (blockIdx.x * 256 + threadIdx.x) >> 5;
        int lane = threadIdx.x & 31;
        int b = warp >> 9, co = warp & 511;
        float sum = 0.f;
        const float* w2 = g_W2 + co * 512;
        const float* sv = g_s + b * 512;
        for (int ci = lane; ci < 512; ci += 32) {
            float s = sv[ci];
            sum += w2[ci] * s * s;
        }
        #pragma unroll
        for (int off = 16; off > 0; off >>= 1) sum += __shfl_xor_sync(0xffffffffu, sum, off);
        if (lane == 0)
            g_alpha[b * 512 + co] = CONV_SCALE / sqrtf(CONV_SCALE * CONV_SCALE * sum + 1e-8f);
    } else {
        int id = blockIdx.x - 1024;                 // 16384 blocks
        int ci0 = (id & 15) * 32, y = (id >> 4) & 63, b = id >> 10;
        int tid = threadIdx.x;
        if (tid < 32) ss[tid] = g_s[b * 512 + ci0 + tid];
        {
            int i = tid >> 3, v = tid & 7;
            const float4* src = reinterpret_cast<const float4*>(
                x + (((size_t)(b * 512 + ci0 + i) * 64 + y) * 64));
            float4 f0 = src[v * 2], f1 = src[v * 2 + 1];
            int c = v * 8;
            sm[i][c+0]=f0.x; sm[i][c+1]=f0.y; sm[i][c+2]=f0.z; sm[i][c+3]=f0.w;
            sm[i][c+4]=f1.x; sm[i][c+5]=f1.y; sm[i][c+6]=f1.z; sm[i][c+7]=f1.w;
        }
        __syncthreads();
        {
            int xc = tid >> 2, g = tid & 3;
            union { __half h[8]; uint4 u; } pk;
            #pragma unroll
            for (int j = 0; j < 8; j++)
                pk.h[j] = __float2half(sm[g * 8 + j][xc] * ss[g * 8 + j]);
            *reinterpret_cast<uint4*>(
                g_Xs + ((size_t)((b * 64 + y) * 64 + xc) * 512) + ci0 + g * 8) = pk.u;
        }
    }
}

// ================= conv kernel: f32-acc mma.sync, occupancy 2 =================
// CTA: 64 co x 256 px (4 rows). 8 warps = 2 m x 4 n (each warp 32co x 64px = 1 row).
// 32 stages of 16 ci; X tile 6x66 px halo, rows padded to 24 halfs (48B, conflict-free).

#define XB_HALFS (396 * 24)   /* 9504  -> 19008 B */
#define WB_HALFS (576 * 24)   /* 13824 -> 27648 B */
#define XB_BYTES (XB_HALFS * 2)
#define WB_BYTES (WB_HALFS * 2)
#define SMEM_BYTES (2 * (XB_BYTES + WB_BYTES))   /* 93312 */

__device__ __forceinline__ void cp16(uint32_t dst, const void* src, int sz) {
    asm volatile("cp.async.cg.shared.global [%0], [%1], 16, %2;"
                 :: "r"(dst), "l"(src), "r"(sz) : "memory");
}
__device__ __forceinline__ void cp_commit() {
    asm volatile("cp.async.commit_group;" ::: "memory");
}
__device__ __forceinline__ void ldsm4(uint32_t r[4], uint32_t addr) {
    asm volatile("ldmatrix.sync.aligned.m8n8.x4.shared.b16 {%0,%1,%2,%3}, [%4];"
                 : "=r"(r[0]), "=r"(r[1]), "=r"(r[2]), "=r"(r[3]) : "r"(addr));
}
__device__ __forceinline__ void mma_f16(float acc[4], const uint32_t a[4], const uint32_t b2[2]) {
    asm volatile(
        "mma.sync.aligned.m16n8k16.row.col.f32.f16.f16.f32 "
        "{%0,%1,%2,%3}, {%4,%5,%6,%7}, {%8,%9}, {%0,%1,%2,%3};\n"
        : "+f"(acc[0]), "+f"(acc[1]), "+f"(acc[2]), "+f"(acc[3])
        : "r"(a[0]), "r"(a[1]), "r"(a[2]), "r"(a[3]), "r"(b2[0]), "r"(b2[1]));
}

__device__ __forceinline__ void fill_stage(uint32_t xb, uint32_t wb,
                                           int b, int y0, int co0, int kc, int tid) {
    // X: 396 px (6 rows x 66 cols halo) x 16 ci (2 x 16B) = 792 cp
    // W: 9 taps x 64 co x 16 ci (2 x 16B)                 = 1152 cp
    #pragma unroll
    for (int it = 0; it < 8; it++) {
        int i = tid + it * 256;
        if (i < 792) {
            int v = i & 1, p = i >> 1;
            int r = p / 66, c = p - r * 66;
            int iy = y0 - 1 + r, ix = c - 1;
            int ok = (iy >= 0 && iy < 64 && ix >= 0 && ix < 64) ? 16 : 0;
            int iyc = iy < 0 ? 0 : (iy > 63 ? 63 : iy);
            int ixc = ix < 0 ? 0 : (ix > 63 ? 63 : ix);
            const __half* src = g_Xs + ((size_t)((b * 64 + iyc) * 64 + ixc) * 512 + kc * 16 + v * 8);
            cp16(xb + (uint32_t)(p * 24 + v * 8) * 2, src, ok);
        } else if (i < 792 + 1152) {
            int j = i - 792;
            int v = j & 1, row = j >> 1;            // row = tap*64 + co_l
            int tap = row >> 6, co_l = row & 63;
            const __half* src = g_Wh + ((size_t)(tap * 512 + co0 + co_l) * 512 + kc * 16 + v * 8);
            cp16(wb + (uint32_t)(row * 24 + v * 8) * 2, src, 16);
        }
    }
    cp_commit();
}

__global__ void __launch_bounds__(256, 2) conv_kernel(float* __restrict__ out) {
    extern __shared__ __align__(16) __half sh[];
    const uint32_t sbase = (uint32_t)__cvta_generic_to_shared(sh);
    const uint32_t xoff[2] = { sbase, sbase + XB_BYTES };
    const uint32_t woff[2] = { sbase + 2 * XB_BYTES, sbase + 2 * XB_BYTES + WB_BYTES };

    const int tid = threadIdx.x, lane = tid & 31, warp = tid >> 5;
    const int wm = warp & 1, wn = warp >> 1;       // 2 m-warps x 4 n-warps (1 row each)
    const int b = blockIdx.z, co0 = blockIdx.y * 64, y0 = blockIdx.x * 4;

    // ldmatrix lane address bases (byte offsets, row stride 24 halfs = 48B)
    const int l15 = ((lane >> 3) & 1) * 8 + (lane & 7);
    const int aK  = (lane >> 4) * 8;
    uint32_t aBase[2];
    #pragma unroll
    for (int mf = 0; mf < 2; mf++)
        aBase[mf] = (uint32_t)(((wm * 32 + mf * 16 + l15) * 24 + aK) * 2);
    const int nloc = ((lane >> 4) & 1) * 8 + (lane & 7);
    const int bK   = ((lane >> 3) & 1) * 8;
    uint32_t bBase[4];
    #pragma unroll
    for (int nfp = 0; nfp < 4; nfp++)
        bBase[nfp] = (uint32_t)(((wn * 66 + nfp * 16 + nloc) * 24 + bK) * 2);

    float acc[2][8][4];
    #pragma unroll
    for (int mf = 0; mf < 2; mf++)
        #pragma unroll
        for (int nf = 0; nf < 8; nf++)
            #pragma unroll
            for (int i = 0; i < 4; i++) acc[mf][nf][i] = 0.f;

    fill_stage(xoff[0], woff[0], b, y0, co0, 0, tid);
    fill_stage(xoff[1], woff[1], b, y0, co0, 1, tid);

    for (int s = 0; s < 32; s++) {
        if (s < 31) asm volatile("cp.async.wait_group 1;" ::: "memory");
        else        asm volatile("cp.async.wait_group 0;" ::: "memory");
        __syncthreads();

        const uint32_t xB = xoff[s & 1], wB = woff[s & 1];
        #pragma unroll
        for (int tap = 0; tap < 9; tap++) {
            const int ky = tap / 3, kx = tap - ky * 3;
            const uint32_t tofsA = (uint32_t)(tap * 3072);          // 64 rows * 48B
            const uint32_t tofsB = (uint32_t)((ky * 66 + kx) * 48);
            uint32_t a0[4], a1[4];
            ldsm4(a0, wB + aBase[0] + tofsA);
            ldsm4(a1, wB + aBase[1] + tofsA);
            #pragma unroll
            for (int nfp = 0; nfp < 4; nfp++) {
                uint32_t bb[4];
                ldsm4(bb, xB + bBase[nfp] + tofsB);
                mma_f16(acc[0][2 * nfp],     a0, bb);
                mma_f16(acc[0][2 * nfp + 1], a0, bb + 2);
                mma_f16(acc[1][2 * nfp],     a1, bb);
                mma_f16(acc[1][2 * nfp + 1], a1, bb + 2);
            }
        }
        __syncthreads();
        if (s + 2 < 32) fill_stage(xoff[s & 1], woff[s & 1], b, y0, co0, s + 2, tid);
    }

    // ---- epilogue: out = alpha * acc, NCHW fp32; each warp owns 1 output row ----
    const int row = y0 + wn;
    #pragma unroll
    for (int mf = 0; mf < 2; mf++) {
        int co = co0 + wm * 32 + mf * 16 + (lane >> 2);
        float al0 = g_alpha[b * 512 + co];
        float al1 = g_alpha[b * 512 + co + 8];
        float* o0 = out + ((size_t)(b * 512 + co)) * 4096 + row * 64;
        float* o1 = o0 + 8 * 4096;
        #pragma unroll
        for (int nf = 0; nf < 8; nf++) {
            int col = nf * 8 + (lane & 3) * 2;
            *reinterpret_cast<float2*>(o0 + col) =
                make_float2(al0 * acc[mf][nf][0], al0 * acc[mf][nf][1]);
            *reinterpret_cast<float2*>(o1 + col) =
                make_float2(al1 * acc[mf][nf][2], al1 * acc[mf][nf][3]);
        }
    }
}

// ---------------- launch ----------------
extern "C" void kernel_launch(void* const* d_in, const int* in_sizes, int n_in,
                              void* d_out, int out_size) {
    const float* x     = (const float*)d_in[0];
    const float* style = (const float*)d_in[1];
    const float* weight= (const float*)d_in[2];
    const float* mw    = (const float*)d_in[3];
    const float* mbias = (const float*)d_in[4];
    float* out = (float*)d_out;
    (void)in_sizes; (void)n_in; (void)out_size;

    cudaFuncSetAttribute(conv_kernel, cudaFuncAttributeMaxDynamicSharedMemorySize, SMEM_BYTES);

    prepA_kernel<<<2048, 256>>>(style, mw, mbias, weight);
    prepB_kernel<<<1024 + 16384, 256>>>(x);
    conv_kernel<<<dim3(16, 8, 16), 256, SMEM_BYTES>>>(out);
}

// round 7
// speedup vs baseline: 1.0684x; 1.0684x over previous
#include <cuda_runtime.h>
#include <cuda_fp16.h>
#include <cstdint>

#define MOD_SCALE 0.04419417382415922f   /* 1/sqrt(512) */
#define CONV_SCALE 0.014731391274719739f /* 1/sqrt(512*9) */

// ---------------- device scratch ----------------
__device__ __align__(16) __half g_Xs[16 * 64 * 64 * 512]; // NHWC x*s fp16
__device__ __align__(16) __half g_Wh[9 * 512 * 512];      // [tap][co][ci] fp16
__device__ float  g_W2[512 * 512];
__device__ float  g_s[16 * 512];
__device__ float  g_alpha[16 * 512];

// ---------------- fused kernel A: mod (blocks 0-1023) + weight prep (1024-2047) ----------------
__global__ void prepA_kernel(const float* __restrict__ style,
                             const float* __restrict__ mw,
                             const float* __restrict__ bias,
                             const float* __restrict__ weight) {
    if (blockIdx.x < 1024) {
        int warp = (blockIdx.x * 256 + threadIdx.x) >> 5;
        int lane = threadIdx.x & 31;
        int b = warp >> 9, ci = warp & 511;
        float sum = 0.f;
        const float* st = style + b * 512;
        const float* w  = mw + ci * 512;
        for (int d = lane; d < 512; d += 32) sum += st[d] * w[d];
        #pragma unroll
        for (int off = 16; off > 0; off >>= 1) sum += __shfl_xor_sync(0xffffffffu, sum, off);
        if (lane == 0) g_s[b * 512 + ci] = sum * MOD_SCALE + bias[ci];
    } else {
        int idx = (blockIdx.x - 1024) * 256 + threadIdx.x;  // co*512+ci
        const float* w = weight + (size_t)idx * 9;
        float s2 = 0.f;
        #pragma unroll
        for (int k = 0; k < 9; k++) {
            float v = w[k];
            s2 += v * v;
            g_Wh[k * (512 * 512) + idx] = __float2half(v);
        }
        g_W2[idx] = s2;
    }
}

// ---------------- fused kernel B: demod alpha (blocks 0-1023) + Xs build (1024+) ----------------
__global__ void prepB_kernel(const float* __restrict__ x) {
    __shared__ float sm[32][65];
    __shared__ float ss[32];
    if (blockIdx.x < 1024) {
        int warp = (blockIdx.x * 256 + threadIdx.x) >> 5;
        int lane = threadIdx.x & 31;
        int b = warp >> 9, co = warp & 511;
        float sum = 0.f;
        const float* w2 = g_W2 + co * 512;
        const float* sv = g_s + b * 512;
        for (int ci = lane; ci < 512; ci += 32) {
            float s = sv[ci];
            sum += w2[ci] * s * s;
        }
        #pragma unroll
        for (int off = 16; off > 0; off >>= 1) sum += __shfl_xor_sync(0xffffffffu, sum, off);
        if (lane == 0)
            g_alpha[b * 512 + co] = CONV_SCALE / sqrtf(CONV_SCALE * CONV_SCALE * sum + 1e-8f);
    } else {
        int id = blockIdx.x - 1024;                 // 16384 blocks
        int ci0 = (id & 15) * 32, y = (id >> 4) & 63, b = id >> 10;
        int tid = threadIdx.x;
        if (tid < 32) ss[tid] = g_s[b * 512 + ci0 + tid];
        {
            int i = tid >> 3, v = tid & 7;
            const float4* src = reinterpret_cast<const float4*>(
                x + (((size_t)(b * 512 + ci0 + i) * 64 + y) * 64));
            float4 f0 = src[v * 2], f1 = src[v * 2 + 1];
            int c = v * 8;
            sm[i][c+0]=f0.x; sm[i][c+1]=f0.y; sm[i][c+2]=f0.z; sm[i][c+3]=f0.w;
            sm[i][c+4]=f1.x; sm[i][c+5]=f1.y; sm[i][c+6]=f1.z; sm[i][c+7]=f1.w;
        }
        __syncthreads();
        {
            int xc = tid >> 2, g = tid & 3;
            union { __half h[8]; uint4 u; } pk;
            #pragma unroll
            for (int j = 0; j < 8; j++)
                pk.h[j] = __float2half(sm[g * 8 + j][xc] * ss[g * 8 + j]);
            *reinterpret_cast<uint4*>(
                g_Xs + ((size_t)((b * 64 + y) * 64 + xc) * 512) + ci0 + g * 8) = pk.u;
        }
    }
}

// ================= conv kernel: R3 tiling + 3-deep ring, 1 sync/stage =================
// CTA: 64 co x 512 px (8 rows). 8 warps = 2 m x 4 n. 32 stages of kc=16 ci.
// X tile: 660 px (10x66 halo) x 16 ci, rows padded to 24 halfs (48B, 16B-aligned,
// conflict-free: 8-row LDSM phase hits word-starts {0,12,24,4,16,28,8,20}).
// W tile: 9 taps x 64 co x 16 ci, rows 24 halfs.

#define XB_BYTES (660 * 48)   /* 31680 */
#define WB_BYTES (576 * 48)   /* 27648 */
#define STG_BYTES (XB_BYTES + WB_BYTES)   /* 59328 */
#define SMEM_BYTES (3 * STG_BYTES)        /* 177984 */

__device__ __forceinline__ void cp16(uint32_t dst, const void* src, int sz) {
    asm volatile("cp.async.cg.shared.global [%0], [%1], 16, %2;"
                 :: "r"(dst), "l"(src), "r"(sz) : "memory");
}
__device__ __forceinline__ void ldsm4(uint32_t r[4], uint32_t addr) {
    asm volatile("ldmatrix.sync.aligned.m8n8.x4.shared.b16 {%0,%1,%2,%3}, [%4];"
                 : "=r"(r[0]), "=r"(r[1]), "=r"(r[2]), "=r"(r[3]) : "r"(addr));
}
__device__ __forceinline__ void mma_f16(float acc[4], const uint32_t a[4], const uint32_t b2[2]) {
    asm volatile(
        "mma.sync.aligned.m16n8k16.row.col.f32.f16.f16.f32 "
        "{%0,%1,%2,%3}, {%4,%5,%6,%7}, {%8,%9}, {%0,%1,%2,%3};\n"
        : "+f"(acc[0]), "+f"(acc[1]), "+f"(acc[2]), "+f"(acc[3])
        : "r"(a[0]), "r"(a[1]), "r"(a[2]), "r"(a[3]), "r"(b2[0]), "r"(b2[1]));
}

__global__ void __launch_bounds__(256, 1) conv_kernel(float* __restrict__ out) {
    extern __shared__ __align__(16) __half sh[];
    const uint32_t sbase = (uint32_t)__cvta_generic_to_shared(sh);

    const int tid = threadIdx.x, lane = tid & 31, warp = tid >> 5;
    const int wm = warp & 1, wn = warp >> 1;
    const int b = blockIdx.z, co0 = blockIdx.y * 64, y0 = blockIdx.x * 8;

    // ---- hoisted fill addressing (per-thread, stage-invariant) ----
    // X: 660 px x 2 cp of 16B = 1320 cps; 6 iterations (last partial: tid<40)
    const __half* xsrc[6]; int xok[6]; uint32_t xdst[6];
    #pragma unroll
    for (int it = 0; it < 6; it++) {
        int i = tid + it * 256;
        int ii = i < 1320 ? i : 0;
        int v = ii & 1, p = ii >> 1;
        int r = p / 66, c = p - r * 66;
        int iy = y0 - 1 + r, ix = c - 1;
        int inb = (iy >= 0 && iy < 64 && ix >= 0 && ix < 64);
        int iyc = iy < 0 ? 0 : (iy > 63 ? 63 : iy);
        int ixc = ix < 0 ? 0 : (ix > 63 ? 63 : ix);
        xsrc[it] = g_Xs + ((size_t)((b * 64 + iyc) * 64 + ixc) * 512 + v * 8);
        xok[it]  = inb ? 16 : 0;
        xdst[it] = (uint32_t)((p * 24 + v * 8) * 2);
    }
    // W: 576 rows x 2 cp = 1152 cps; 5 iterations (last partial: tid<128)
    const __half* wsrc[5]; uint32_t wdst[5];
    #pragma unroll
    for (int it = 0; it < 5; it++) {
        int j = tid + it * 256;
        int jj = j < 1152 ? j : 0;
        int v = jj & 1, row = jj >> 1;
        int tap = row >> 6, co_l = row & 63;
        wsrc[it] = g_Wh + ((size_t)(tap * 512 + co0 + co_l) * 512 + v * 8);
        wdst[it] = (uint32_t)((row * 24 + v * 8) * 2);
    }

    // fill stage kc (16 ci) into ring slot rb
    auto fill = [&](int kc, int rb) {
        uint32_t xb = sbase + rb * STG_BYTES;
        uint32_t wb = xb + XB_BYTES;
        int ofs = kc * 16;   // halfs
        #pragma unroll
        for (int it = 0; it < 6; it++)
            if (it < 5 || tid < 40)
                cp16(xb + xdst[it], xsrc[it] + ofs, xok[it]);
        #pragma unroll
        for (int it = 0; it < 5; it++)
            if (it < 4 || tid < 128)
                cp16(wb + wdst[it], wsrc[it] + ofs, 16);
        asm volatile("cp.async.commit_group;" ::: "memory");
    };

    // ---- ldmatrix lane bases (byte offsets, row stride 24 halfs = 48B) ----
    const int l15 = ((lane >> 3) & 1) * 8 + (lane & 7);
    const int aK  = (lane >> 4) * 8;
    uint32_t aBase[2];
    #pragma unroll
    for (int mf = 0; mf < 2; mf++)
        aBase[mf] = (uint32_t)(((wm * 32 + mf * 16 + l15) * 24 + aK) * 2);
    const int nloc = ((lane >> 4) & 1) * 8 + (lane & 7);
    const int bK   = ((lane >> 3) & 1) * 8;
    uint32_t bBase[8];
    #pragma unroll
    for (int nfp = 0; nfp < 8; nfp++) {
        int px = wn * 128 + nfp * 16 + nloc;
        bBase[nfp] = (uint32_t)((((px >> 6) * 66 + (px & 63)) * 24 + bK) * 2);
    }

    float acc[2][16][4];
    #pragma unroll
    for (int mf = 0; mf < 2; mf++)
        #pragma unroll
        for (int nf = 0; nf < 16; nf++)
            #pragma unroll
            for (int i = 0; i < 4; i++) acc[mf][nf][i] = 0.f;

    // prologue: stages 0,1 into slots 0,1
    fill(0, 0);
    fill(1, 1);

    int rb = 0, rbf = 2;
    for (int s = 0; s < 32; s++) {
        if (s < 31) asm volatile("cp.async.wait_group 1;" ::: "memory");
        else        asm volatile("cp.async.wait_group 0;" ::: "memory");
        __syncthreads();

        if (s + 2 < 32) {
            fill(s + 2, rbf);
            if (++rbf == 3) rbf = 0;
        }

        const uint32_t xB = sbase + rb * STG_BYTES;
        const uint32_t wB = xB + XB_BYTES;
        #pragma unroll
        for (int tap = 0; tap < 9; tap++) {
            const int ky = tap / 3, kx = tap - ky * 3;
            const uint32_t tofsA = (uint32_t)(tap * 3072);          // 64 rows * 48B
            const uint32_t tofsB = (uint32_t)((ky * 66 + kx) * 48);
            uint32_t a0[4], a1[4];
            ldsm4(a0, wB + aBase[0] + tofsA);
            ldsm4(a1, wB + aBase[1] + tofsA);
            #pragma unroll
            for (int nfp = 0; nfp < 8; nfp++) {
                uint32_t bb[4];
                ldsm4(bb, xB + bBase[nfp] + tofsB);
                mma_f16(acc[0][2 * nfp],     a0, bb);
                mma_f16(acc[0][2 * nfp + 1], a0, bb + 2);
                mma_f16(acc[1][2 * nfp],     a1, bb);
                mma_f16(acc[1][2 * nfp + 1], a1, bb + 2);
            }
        }
        if (++rb == 3) rb = 0;
    }

    // ---- epilogue: out = alpha * acc, NCHW fp32 ----
    #pragma unroll
    for (int mf = 0; mf < 2; mf++) {
        int cobase = co0 + wm * 32 + mf * 16 + (lane >> 2);
        float al0 = g_alpha[b * 512 + cobase];
        float al1 = g_alpha[b * 512 + cobase + 8];
        float* o0 = out + ((size_t)(b * 512 + cobase)) * 4096;
        float* o1 = o0 + 8 * 4096;
        #pragma unroll
        for (int nf = 0; nf < 16; nf++) {
            int px = wn * 128 + nf * 8 + (lane & 3) * 2;
            int ofs = (y0 + (px >> 6)) * 64 + (px & 63);
            *reinterpret_cast<float2*>(o0 + ofs) =
                make_float2(al0 * acc[mf][nf][0], al0 * acc[mf][nf][1]);
            *reinterpret_cast<float2*>(o1 + ofs) =
                make_float2(al1 * acc[mf][nf][2], al1 * acc[mf][nf][3]);
        }
    }
}

// ---------------- launch ----------------
extern "C" void kernel_launch(void* const* d_in, const int* in_sizes, int n_in,
                              void* d_out, int out_size) {
    const float* x     = (const float*)d_in[0];
    const float* style = (const float*)d_in[1];
    const float* weight= (const float*)d_in[2];
    const float* mw    = (const float*)d_in[3];
    const float* mbias = (const float*)d_in[4];
    float* out = (float*)d_out;
    (void)in_sizes; (void)n_in; (void)out_size;

    cudaFuncSetAttribute(conv_kernel, cudaFuncAttributeMaxDynamicSharedMemorySize, SMEM_BYTES);

    prepA_kernel<<<2048, 256>>>(style, mw, mbias, weight);
    prepB_kernel<<<1024 + 16384, 256>>>(x);
    conv_kernel<<<dim3(8, 8, 16), 256, SMEM_BYTES>>>(out);
}

// round 8
// speedup vs baseline: 1.1347x; 1.0621x over previous
#include <cuda_runtime.h>
#include <cuda_fp16.h>
#include <cstdint>

#define MOD_SCALE 0.04419417382415922f   /* 1/sqrt(512) */
#define CONV_SCALE 0.014731391274719739f /* 1/sqrt(512*9) */

// ---------------- device scratch ----------------
__device__ __align__(16) __half g_Xs[16 * 64 * 64 * 512]; // NHWC x*s fp16
__device__ __align__(16) __half g_Wh[9 * 512 * 512];      // [tap][co][ci] fp16
__device__ float  g_W2[512 * 512];
__device__ float  g_s[16 * 512];
__device__ float  g_alpha[16 * 512];

// ---------------- fused kernel A: mod (blocks 0-1023) + weight prep (1024-2047) ----------------
__global__ void prepA_kernel(const float* __restrict__ style,
                             const float* __restrict__ mw,
                             const float* __restrict__ bias,
                             const float* __restrict__ weight) {
    if (blockIdx.x < 1024) {
        int warp = (blockIdx.x * 256 + threadIdx.x) >> 5;
        int lane = threadIdx.x & 31;
        int b = warp >> 9, ci = warp & 511;
        float sum = 0.f;
        const float* st = style + b * 512;
        const float* w  = mw + ci * 512;
        for (int d = lane; d < 512; d += 32) sum += st[d] * w[d];
        #pragma unroll
        for (int off = 16; off > 0; off >>= 1) sum += __shfl_xor_sync(0xffffffffu, sum, off);
        if (lane == 0) g_s[b * 512 + ci] = sum * MOD_SCALE + bias[ci];
    } else {
        int idx = (blockIdx.x - 1024) * 256 + threadIdx.x;  // co*512+ci
        const float* w = weight + (size_t)idx * 9;
        float s2 = 0.f;
        #pragma unroll
        for (int k = 0; k < 9; k++) {
            float v = w[k];
            s2 += v * v;
            g_Wh[k * (512 * 512) + idx] = __float2half(v);
        }
        g_W2[idx] = s2;
    }
}

// ---------------- fused kernel B: demod alpha (blocks 0-1023) + Xs build (1024+) ----------------
__global__ void prepB_kernel(const float* __restrict__ x) {
    __shared__ float sm[32][65];
    __shared__ float ss[32];
    if (blockIdx.x < 1024) {
        int warp = (blockIdx.x * 256 + threadIdx.x) >> 5;
        int lane = threadIdx.x & 31;
        int b = warp >> 9, co = warp & 511;
        float sum = 0.f;
        const float* w2 = g_W2 + co * 512;
        const float* sv = g_s + b * 512;
        for (int ci = lane; ci < 512; ci += 32) {
            float s = sv[ci];
            sum += w2[ci] * s * s;
        }
        #pragma unroll
        for (int off = 16; off > 0; off >>= 1) sum += __shfl_xor_sync(0xffffffffu, sum, off);
        if (lane == 0)
            g_alpha[b * 512 + co] = CONV_SCALE / sqrtf(CONV_SCALE * CONV_SCALE * sum + 1e-8f);
    } else {
        int id = blockIdx.x - 1024;                 // 16384 blocks
        int ci0 = (id & 15) * 32, y = (id >> 4) & 63, b = id >> 10;
        int tid = threadIdx.x;
        if (tid < 32) ss[tid] = g_s[b * 512 + ci0 + tid];
        {
            int i = tid >> 3, v = tid & 7;
            const float4* src = reinterpret_cast<const float4*>(
                x + (((size_t)(b * 512 + ci0 + i) * 64 + y) * 64));
            float4 f0 = src[v * 2], f1 = src[v * 2 + 1];
            int c = v * 8;
            sm[i][c+0]=f0.x; sm[i][c+1]=f0.y; sm[i][c+2]=f0.z; sm[i][c+3]=f0.w;
            sm[i][c+4]=f1.x; sm[i][c+5]=f1.y; sm[i][c+6]=f1.z; sm[i][c+7]=f1.w;
        }
        __syncthreads();
        {
            int xc = tid >> 2, g = tid & 3;
            union { __half h[8]; uint4 u; } pk;
            #pragma unroll
            for (int j = 0; j < 8; j++)
                pk.h[j] = __float2half(sm[g * 8 + j][xc] * ss[g * 8 + j]);
            *reinterpret_cast<uint4*>(
                g_Xs + ((size_t)((b * 64 + y) * 64 + xc) * 512) + ci0 + g * 8) = pk.u;
        }
    }
}

// ================= conv kernel: R3 tiling + software-pipelined operands =================
// CTA: 64 co x 512 px (8 rows). 8 warps = 2 m x 4 n. 16 stages of kc=32 ci.
// X: 660 px (10x66 halo), rows padded to 40 halfs (80B). W: 9 taps x 64 co, 40-half rows.
// Inner loop: 18 steps (tap,ks); A-frags for step t+1 and B-frag for next nfp are
// ldmatrix'd one batch ahead (double-buffered) so HMMA never waits on LDSM latency.

#define XB_HALFS (660 * 40)   /* 26400 -> 52800 B */
#define WB_HALFS (576 * 40)   /* 23040 -> 46080 B */
#define XB_BYTES (XB_HALFS * 2)
#define WB_BYTES (WB_HALFS * 2)
#define SMEM_BYTES (2 * XB_BYTES + 2 * WB_BYTES)   /* 197760 */

__device__ __forceinline__ void cp16(uint32_t dst, const void* src, int sz) {
    asm volatile("cp.async.cg.shared.global [%0], [%1], 16, %2;"
                 :: "r"(dst), "l"(src), "r"(sz) : "memory");
}
__device__ __forceinline__ void cp_commit() {
    asm volatile("cp.async.commit_group;" ::: "memory");
}
__device__ __forceinline__ void ldsm4(uint32_t r[4], uint32_t addr) {
    asm volatile("ldmatrix.sync.aligned.m8n8.x4.shared.b16 {%0,%1,%2,%3}, [%4];"
                 : "=r"(r[0]), "=r"(r[1]), "=r"(r[2]), "=r"(r[3]) : "r"(addr));
}
__device__ __forceinline__ void mma_f16(float acc[4], const uint32_t a[4], const uint32_t b2[2]) {
    asm volatile(
        "mma.sync.aligned.m16n8k16.row.col.f32.f16.f16.f32 "
        "{%0,%1,%2,%3}, {%4,%5,%6,%7}, {%8,%9}, {%0,%1,%2,%3};\n"
        : "+f"(acc[0]), "+f"(acc[1]), "+f"(acc[2]), "+f"(acc[3])
        : "r"(a[0]), "r"(a[1]), "r"(a[2]), "r"(a[3]), "r"(b2[0]), "r"(b2[1]));
}

__device__ __forceinline__ void fill_stage(uint32_t xb, uint32_t wb,
                                           int b, int y0, int co0, int kc, int tid) {
    // X tile: 660 pixels x 32 ci (4 x 16B each)
    #pragma unroll
    for (int it = 0; it < 11; it++) {
        int i = tid + it * 256;
        if (i < 2640) {
            int v = i & 3, p = i >> 2;
            int r = p / 66, c = p - r * 66;
            int iy = y0 - 1 + r, ix = c - 1;
            int ok = (iy >= 0 && iy < 64 && ix >= 0 && ix < 64) ? 16 : 0;
            int iyc = iy < 0 ? 0 : (iy > 63 ? 63 : iy);
            int ixc = ix < 0 ? 0 : (ix > 63 ? 63 : ix);
            const __half* src = g_Xs + ((size_t)((b * 64 + iyc) * 64 + ixc) * 512 + kc * 32 + v * 8);
            cp16(xb + (uint32_t)(p * 40 + v * 8) * 2, src, ok);
        }
    }
    // W tile: 9 taps x 64 co x 32 ci
    #pragma unroll
    for (int it = 0; it < 9; it++) {
        int i = tid + it * 256;     // 2304 total, exact
        int v = i & 3, row = i >> 2;
        int tap = row >> 6, co_l = row & 63;
        const __half* src = g_Wh + ((size_t)(tap * 512 + co0 + co_l) * 512 + kc * 32 + v * 8);
        cp16(wb + (uint32_t)(row * 40 + v * 8) * 2, src, 16);
    }
    cp_commit();
}

__global__ void __launch_bounds__(256, 1) conv_kernel(float* __restrict__ out) {
    extern __shared__ __align__(16) __half sh[];
    const uint32_t sbase = (uint32_t)__cvta_generic_to_shared(sh);
    const uint32_t xoff[2] = { sbase, sbase + XB_BYTES };
    const uint32_t woff[2] = { sbase + 2 * XB_BYTES, sbase + 2 * XB_BYTES + WB_BYTES };

    const int tid = threadIdx.x, lane = tid & 31, warp = tid >> 5;
    const int wm = warp & 1, wn = warp >> 1;
    const int b = blockIdx.z, co0 = blockIdx.y * 64, y0 = blockIdx.x * 8;

    // ldmatrix lane address bases (byte offsets, row stride 40 halfs = 80B)
    const int l15 = ((lane >> 3) & 1) * 8 + (lane & 7);
    const int aK  = (lane >> 4) * 8;
    uint32_t aBase[2];
    #pragma unroll
    for (int mf = 0; mf < 2; mf++)
        aBase[mf] = (uint32_t)(((wm * 32 + mf * 16 + l15) * 40 + aK) * 2);
    const int nloc = ((lane >> 4) & 1) * 8 + (lane & 7);
    const int bK   = ((lane >> 3) & 1) * 8;
    uint32_t bBase[8];
    #pragma unroll
    for (int nfp = 0; nfp < 8; nfp++) {
        int px = wn * 128 + nfp * 16 + nloc;
        bBase[nfp] = (uint32_t)((((px >> 6) * 66 + (px & 63)) * 40 + bK) * 2);
    }

    float acc[2][16][4];
    #pragma unroll
    for (int mf = 0; mf < 2; mf++)
        #pragma unroll
        for (int nf = 0; nf < 16; nf++)
            #pragma unroll
            for (int i = 0; i < 4; i++) acc[mf][nf][i] = 0.f;

    // prologue: prefetch stages 0,1
    fill_stage(xoff[0], woff[0], b, y0, co0, 0, tid);
    fill_stage(xoff[1], woff[1], b, y0, co0, 1, tid);

    for (int s = 0; s < 16; s++) {
        if (s < 15) asm volatile("cp.async.wait_group 1;" ::: "memory");
        else        asm volatile("cp.async.wait_group 0;" ::: "memory");
        __syncthreads();

        const uint32_t xB = xoff[s & 1], wB = woff[s & 1];

        // step t = tap*2 + ks; compile-time offsets (fully unrolled)
        #define AOFS(t, h) (wB + aBase[h] + (uint32_t)(((t) >> 1) * 5120 + ((t) & 1) * 32))
        #define BOFS(t, nfp) (xB + bBase[nfp] + \
            (uint32_t)(((((t) >> 1) / 3) * 66 + (((t) >> 1) % 3)) * 80 + ((t) & 1) * 32))

        uint32_t aa[2][2][4];   // [buf][mf][frag]
        uint32_t bb[2][4];      // [buf][frag]
        ldsm4(aa[0][0], AOFS(0, 0));
        ldsm4(aa[0][1], AOFS(0, 1));
        ldsm4(bb[0], BOFS(0, 0));

        #pragma unroll
        for (int t = 0; t < 18; t++) {
            const int ct = t & 1, nt = ct ^ 1;
            if (t < 17) {
                ldsm4(aa[nt][0], AOFS(t + 1, 0));
                ldsm4(aa[nt][1], AOFS(t + 1, 1));
            }
            #pragma unroll
            for (int nfp = 0; nfp < 8; nfp++) {
                const int cb = nfp & 1, nb = cb ^ 1;
                if (nfp < 7)        ldsm4(bb[nb], BOFS(t, nfp + 1));
                else if (t < 17)    ldsm4(bb[nb], BOFS(t + 1, 0));
                mma_f16(acc[0][2 * nfp],     aa[ct][0], bb[cb]);
                mma_f16(acc[0][2 * nfp + 1], aa[ct][0], bb[cb] + 2);
                mma_f16(acc[1][2 * nfp],     aa[ct][1], bb[cb]);
                mma_f16(acc[1][2 * nfp + 1], aa[ct][1], bb[cb] + 2);
            }
        }
        #undef AOFS
        #undef BOFS

        __syncthreads();
        if (s + 2 < 16) fill_stage(xoff[s & 1], woff[s & 1], b, y0, co0, s + 2, tid);
    }

    // ---- epilogue: out = alpha * acc, NCHW fp32 ----
    #pragma unroll
    for (int mf = 0; mf < 2; mf++) {
        int cobase = co0 + wm * 32 + mf * 16 + (lane >> 2);
        float al0 = g_alpha[b * 512 + cobase];
        float al1 = g_alpha[b * 512 + cobase + 8];
        float* o0 = out + ((size_t)(b * 512 + cobase)) * 4096;
        float* o1 = o0 + 8 * 4096;
        #pragma unroll
        for (int nf = 0; nf < 16; nf++) {
            int px = wn * 128 + nf * 8 + (lane & 3) * 2;
            int ofs = (y0 + (px >> 6)) * 64 + (px & 63);
            *reinterpret_cast<float2*>(o0 + ofs) =
                make_float2(al0 * acc[mf][nf][0], al0 * acc[mf][nf][1]);
            *reinterpret_cast<float2*>(o1 + ofs) =
                make_float2(al1 * acc[mf][nf][2], al1 * acc[mf][nf][3]);
        }
    }
}

// ---------------- launch ----------------
extern "C" void kernel_launch(void* const* d_in, const int* in_sizes, int n_in,
                              void* d_out, int out_size) {
    const float* x     = (const float*)d_in[0];
    const float* style = (const float*)d_in[1];
    const float* weight= (const float*)d_in[2];
    const float* mw    = (const float*)d_in[3];
    const float* mbias = (const float*)d_in[4];
    float* out = (float*)d_out;
    (void)in_sizes; (void)n_in; (void)out_size;

    cudaFuncSetAttribute(conv_kernel, cudaFuncAttributeMaxDynamicSharedMemorySize, SMEM_BYTES);

    prepA_kernel<<<2048, 256>>>(style, mw, mbias, weight);
    prepB_kernel<<<1024 + 16384, 256>>>(x);
    conv_kernel<<<dim3(8, 8, 16), 256, SMEM_BYTES>>>(out);
}